// round 1
// baseline (speedup 1.0000x reference)
#include <cuda_runtime.h>
#include <cstdint>

// ---------------------------------------------------------------------------
// E3NN lifting tensor product: per l in {0,1,2}
//   out[n, ooff + w*dl + i] = (1/8) * sum_u x[n, xoff + u*dl + i] * W_l[u, w]
// Three GEMM-shaped kernels (K=64, 256 out channels), f32x2 packed FMA.
// ---------------------------------------------------------------------------

constexpr int KDIM = 64;    // mul_in
constexpr int WOUT = 256;   // mul_out
constexpr int XROW = 576;   // input row stride (floats)
constexpr int OROW = 2304;  // output row stride (floats)

// DL = 2l+1, J = columns (n,i) per CTA (multiple of DL), JT = columns/thread-group
template <int DL, int J, int JT>
__global__ __launch_bounds__(256, 2)
void tp_kernel(const float* __restrict__ x, const float* __restrict__ W,
               float* __restrict__ out, int xoff, int ooff, int Ntot) {
    extern __shared__ float smem[];
    float* Ws = smem;                 // [64][256] = 64 KB
    float* Bs = smem + KDIM * WOUT;   // [64][J]

    const int tid = threadIdx.x;
    constexpr int NPC = J / DL;       // rows n per CTA
    const int n0 = blockIdx.x * NPC;

    // ---- stage W (row-major [64][256]) into smem, vectorized ----
    {
        const float4* Wg = reinterpret_cast<const float4*>(W);
        float4* Wv = reinterpret_cast<float4*>(Ws);
        #pragma unroll
        for (int k = 0; k < (KDIM * WOUT / 4) / 256; ++k)
            Wv[k * 256 + tid] = Wg[k * 256 + tid];
    }

    // ---- stage x slice into Bs[u][ (n-n0)*DL + i ] ----
    {
        const float* xb = x + (size_t)n0 * XROW + xoff;
        constexpr int PER_N = KDIM * DL;   // contiguous floats per row n
        for (int t = tid; t < KDIM * J; t += 256) {
            int n_rel = t / PER_N;
            int s = t - n_rel * PER_N;     // = u*DL + i
            int u = s / DL;
            int i = s - u * DL;
            float v = 0.f;
            if (n0 + n_rel < Ntot) v = xb[(size_t)n_rel * XROW + s];
            Bs[u * J + n_rel * DL + i] = v;
        }
    }
    __syncthreads();

    const int lane = tid & 31;
    const int jg = tid >> 5;          // 8 column groups (one per warp)
    const int jbase = jg * JT;

    unsigned long long acc[4][JT];    // f32x2 accumulators: pairs (w, w+1)
    #pragma unroll
    for (int p = 0; p < 4; ++p)
        #pragma unroll
        for (int q = 0; q < JT; ++q) acc[p][q] = 0ULL;

    #pragma unroll 8
    for (int u = 0; u < KDIM; ++u) {
        // W pairs: w = p*64 + 2*lane (+1). LDS.64, conflict-free (lane stride 2 words)
        unsigned long long wp[4];
        #pragma unroll
        for (int p = 0; p < 4; ++p) {
            float2 w2 = *reinterpret_cast<const float2*>(Ws + u * WOUT + p * 64 + 2 * lane);
            asm("mov.b64 %0, {%1, %2};"
                : "=l"(wp[p])
                : "r"(__float_as_uint(w2.x)), "r"(__float_as_uint(w2.y)));
        }
        // B values: warp-uniform broadcast loads, duplicated into both halves
        unsigned long long bb[JT];
        #pragma unroll
        for (int q = 0; q < JT; ++q) {
            float b = Bs[u * J + jbase + q];
            asm("mov.b64 %0, {%1, %1};"
                : "=l"(bb[q]) : "r"(__float_as_uint(b)));
        }
        // packed FMA: 2 fp32 FMAs per instruction
        #pragma unroll
        for (int p = 0; p < 4; ++p)
            #pragma unroll
            for (int q = 0; q < JT; ++q)
                asm("fma.rn.f32x2 %0, %1, %2, %0;"
                    : "+l"(acc[p][q]) : "l"(wp[p]), "l"(bb[q]));
    }

    // ---- epilogue: scale by 1/sqrt(64) and store ----
    const float scale = 0.125f;
    #pragma unroll
    for (int q = 0; q < JT; ++q) {
        int j = jbase + q;
        int n_rel = j / DL;
        int i = j - n_rel * DL;
        if (n0 + n_rel >= Ntot) continue;
        float* ob = out + (size_t)(n0 + n_rel) * OROW + ooff + i;
        #pragma unroll
        for (int p = 0; p < 4; ++p) {
            unsigned int ulo, uhi;
            asm("mov.b64 {%0, %1}, %2;" : "=r"(ulo), "=r"(uhi) : "l"(acc[p][q]));
            float lo = __uint_as_float(ulo) * scale;
            float hi = __uint_as_float(uhi) * scale;
            int w = p * 64 + 2 * lane;
            if (DL == 1) {
                // adjacent w, w+1 are adjacent addresses -> 8B store
                *reinterpret_cast<float2*>(ob + w) = make_float2(lo, hi);
            } else {
                ob[w * DL] = lo;
                ob[(w + 1) * DL] = hi;
            }
        }
    }
}

extern "C" void kernel_launch(void* const* d_in, const int* in_sizes, int n_in,
                              void* d_out, int out_size) {
    const float* x  = (const float*)d_in[0];
    const float* W0 = (const float*)d_in[1];
    const float* W1 = (const float*)d_in[2];
    const float* W2 = (const float*)d_in[3];
    float* out = (float*)d_out;

    const int N = in_sizes[0] / XROW;   // 100000

    const int smem40 = (KDIM * WOUT + KDIM * 40) * (int)sizeof(float); // 75776
    const int smem48 = (KDIM * WOUT + KDIM * 48) * (int)sizeof(float); // 77824

    cudaFuncSetAttribute(tp_kernel<1, 40, 5>,
                         cudaFuncAttributeMaxDynamicSharedMemorySize, smem40);
    cudaFuncSetAttribute(tp_kernel<3, 48, 6>,
                         cudaFuncAttributeMaxDynamicSharedMemorySize, smem48);
    cudaFuncSetAttribute(tp_kernel<5, 40, 5>,
                         cudaFuncAttributeMaxDynamicSharedMemorySize, smem40);

    // rows-per-CTA: 40, 16, 8  -> grids 2500 / 6250 / 12500 (exact for N=100000)
    const int g0 = (N + 39) / 40;
    const int g1 = (N + 15) / 16;
    const int g2 = (N + 7)  / 8;

    tp_kernel<1, 40, 5><<<g0, 256, smem40>>>(x, W0, out,   0,    0, N);
    tp_kernel<3, 48, 6><<<g1, 256, smem48>>>(x, W1, out,  64,  256, N);
    tp_kernel<5, 40, 5><<<g2, 256, smem40>>>(x, W2, out, 256, 1024, N);
}

// round 3
// speedup vs baseline: 1.6989x; 1.6989x over previous
#include <cuda_runtime.h>
#include <cuda_bf16.h>
#include <cstdint>

// ---------------------------------------------------------------------------
// E3NN lifting TP as 3 GEMMs on tensor cores (mma.sync bf16, 3-term hi/lo
// split for fp32-grade accuracy):
//   per l: C[M,256] = A[M,64] * W_l[64,256],  M = N*(2l+1)
//   row m = n*d + i maps to x[n, xoff + u*d + i] and out[n, ooff + w*d + i]
// ---------------------------------------------------------------------------

constexpr int XROW = 576;
constexpr int OROW = 2304;
constexpr int KDIM = 64;
constexpr int WOUT = 256;
constexpr int LDA  = 72;    // padded smem row stride (bf16 elems), 144B
constexpr int LDC  = 132;   // padded C smem row stride (f32 elems)
constexpr int SMEM_BYTES = 4 * 128 * LDA * 2;  // 73728 (Ah,Al,Wh,Wl); Cs aliases

// Pre-transposed, hi/lo-split weights: [l][0=hi,1=lo][w][u]
__device__ __align__(16) __nv_bfloat16 g_Wt[3][2][WOUT][KDIM];

__global__ void prep_w(const float* __restrict__ W0, const float* __restrict__ W1,
                       const float* __restrict__ W2) {
    int idx = blockIdx.x * blockDim.x + threadIdx.x;
    if (idx >= 3 * KDIM * WOUT) return;
    int l = idx / (KDIM * WOUT);
    int r = idx - l * (KDIM * WOUT);
    int u = r >> 8;
    int w = r & 255;
    const float* W = (l == 0) ? W0 : (l == 1) ? W1 : W2;
    float v = W[u * WOUT + w];
    __nv_bfloat16 hi = __float2bfloat16(v);
    g_Wt[l][0][w][u] = hi;
    g_Wt[l][1][w][u] = __float2bfloat16(v - __bfloat162float(hi));
}

__device__ __forceinline__ void ldsm_x4(uint32_t addr, uint32_t& r0, uint32_t& r1,
                                        uint32_t& r2, uint32_t& r3) {
    asm volatile("ldmatrix.sync.aligned.m8n8.x4.shared.b16 {%0,%1,%2,%3}, [%4];"
                 : "=r"(r0), "=r"(r1), "=r"(r2), "=r"(r3) : "r"(addr));
}
__device__ __forceinline__ void ldsm_x2(uint32_t addr, uint32_t& r0, uint32_t& r1) {
    asm volatile("ldmatrix.sync.aligned.m8n8.x2.shared.b16 {%0,%1}, [%2];"
                 : "=r"(r0), "=r"(r1) : "r"(addr));
}
__device__ __forceinline__ void mma_bf16(float* c, const uint32_t* a,
                                         uint32_t b0, uint32_t b1) {
    asm volatile("mma.sync.aligned.m16n8k16.row.col.f32.bf16.bf16.f32 "
                 "{%0,%1,%2,%3}, {%4,%5,%6,%7}, {%8,%9}, {%0,%1,%2,%3};"
                 : "+f"(c[0]), "+f"(c[1]), "+f"(c[2]), "+f"(c[3])
                 : "r"(a[0]), "r"(a[1]), "r"(a[2]), "r"(a[3]), "r"(b0), "r"(b1));
}

template <int DL>
__global__ __launch_bounds__(256, 2)
void tp_mma(const float* __restrict__ x, float* __restrict__ out,
            int lsel, int xoff, int ooff, int Mtot) {
    extern __shared__ char smem[];
    __nv_bfloat16* Ah = (__nv_bfloat16*)smem;        // [128][72]
    __nv_bfloat16* Al = Ah + 128 * LDA;
    __nv_bfloat16* Wh = Al + 128 * LDA;              // [128 w][72 u]
    __nv_bfloat16* Wl = Wh + 128 * LDA;
    float* Cs = (float*)smem;                        // [128][132] alias (67584B)

    const int tid = threadIdx.x;
    const int m0  = blockIdx.y * 128;
    const int wb  = blockIdx.x * 128;

    // ---- stage A: x rows -> bf16 hi/lo, layout [m_rel][u] ----
    #pragma unroll 4
    for (int t = tid; t < 128 * 64; t += 256) {
        int mr = t >> 6, u = t & 63;
        int m = m0 + mr;
        float v = 0.f;
        if (m < Mtot) {
            int n = m / DL, i = m - n * DL;
            v = x[(size_t)n * XROW + xoff + u * DL + i];
        }
        __nv_bfloat16 hi = __float2bfloat16(v);
        Ah[mr * LDA + u] = hi;
        Al[mr * LDA + u] = __float2bfloat16(v - __bfloat162float(hi));
    }
    // ---- stage W tile (pre-split [w][u]), 8B vector copies ----
    {
        const uint2* sh = (const uint2*)&g_Wt[lsel][0][wb][0];
        const uint2* sl = (const uint2*)&g_Wt[lsel][1][wb][0];
        #pragma unroll 4
        for (int t = tid; t < 128 * 16; t += 256) {
            int j = t >> 4, u4 = t & 15;
            *(uint2*)&Wh[j * LDA + u4 * 4] = sh[j * 16 + u4];
            *(uint2*)&Wl[j * LDA + u4 * 4] = sl[j * 16 + u4];
        }
    }
    __syncthreads();

    // ---- mma mainloop ----
    const int lane = tid & 31, wid = tid >> 5;
    const int wm = wid & 3, wn = wid >> 2;            // warp grid 4(M) x 2(N)

    const uint32_t sAh = (uint32_t)__cvta_generic_to_shared(Ah);
    const uint32_t sAl = (uint32_t)__cvta_generic_to_shared(Al);
    const uint32_t sWh = (uint32_t)__cvta_generic_to_shared(Wh);
    const uint32_t sWl = (uint32_t)__cvta_generic_to_shared(Wl);

    // ldmatrix lane address offsets (bytes)
    const uint32_t a_off = ((wm * 32 + (lane & 15)) * LDA + (lane >> 4) * 8) * 2;
    const uint32_t b_off = ((wn * 64 + (lane & 7)) * LDA + ((lane >> 3) & 1) * 8) * 2;

    float acc[2][8][4];
    #pragma unroll
    for (int mm = 0; mm < 2; ++mm)
        #pragma unroll
        for (int nn = 0; nn < 8; ++nn)
            #pragma unroll
            for (int q = 0; q < 4; ++q) acc[mm][nn][q] = 0.f;

    #pragma unroll
    for (int kk = 0; kk < 4; ++kk) {
        uint32_t ah[2][4], al[2][4];
        ldsm_x4(sAh + a_off + kk * 32,                 ah[0][0], ah[0][1], ah[0][2], ah[0][3]);
        ldsm_x4(sAh + a_off + kk * 32 + 16 * LDA * 2,  ah[1][0], ah[1][1], ah[1][2], ah[1][3]);
        ldsm_x4(sAl + a_off + kk * 32,                 al[0][0], al[0][1], al[0][2], al[0][3]);
        ldsm_x4(sAl + a_off + kk * 32 + 16 * LDA * 2,  al[1][0], al[1][1], al[1][2], al[1][3]);
        #pragma unroll
        for (int nn = 0; nn < 8; ++nn) {
            uint32_t bh0, bh1, bl0, bl1;
            ldsm_x2(sWh + b_off + kk * 32 + nn * 8 * LDA * 2, bh0, bh1);
            ldsm_x2(sWl + b_off + kk * 32 + nn * 8 * LDA * 2, bl0, bl1);
            #pragma unroll
            for (int mm = 0; mm < 2; ++mm) {
                mma_bf16(acc[mm][nn], ah[mm], bh0, bh1);  // hi*Whi
                mma_bf16(acc[mm][nn], al[mm], bh0, bh1);  // lo*Whi
                mma_bf16(acc[mm][nn], ah[mm], bl0, bl1);  // hi*Wlo
            }
        }
    }

    // ---- epilogue: frags -> smem (scaled), then coalesced global stores ----
    __syncthreads();   // everyone done reading A/W smem before aliasing as Cs
    const float scale = 0.125f;  // 1/sqrt(64)
    #pragma unroll
    for (int mm = 0; mm < 2; ++mm)
        #pragma unroll
        for (int nn = 0; nn < 8; ++nn) {
            int row = wm * 32 + mm * 16 + (lane >> 2);
            int col = wn * 64 + nn * 8 + (lane & 3) * 2;
            *(float2*)&Cs[row * LDC + col] =
                make_float2(acc[mm][nn][0] * scale, acc[mm][nn][1] * scale);
            *(float2*)&Cs[(row + 8) * LDC + col] =
                make_float2(acc[mm][nn][2] * scale, acc[mm][nn][3] * scale);
        }
    __syncthreads();

    if (DL == 1) {
        // m == n; rows contiguous in out: float4 stores
        #pragma unroll 4
        for (int t = tid; t < 128 * 32; t += 256) {
            int row = t >> 5, c4 = (t & 31) * 4;
            int m = m0 + row;
            if (m < Mtot) {
                float4 v = *(float4*)&Cs[row * LDC + c4];
                *(float4*)&out[(size_t)m * OROW + ooff + wb + c4] = v;
            }
        }
    } else {
        // per-n contiguous spans of 128*DL floats at out[n*OROW + ooff + wb*DL]
        int mhi = min(m0 + 128, Mtot);
        int nfirst = m0 / DL;
        int nlast  = (mhi - 1) / DL;
        for (int n = nfirst; n <= nlast; ++n) {
            int ilo = max(0, m0 - n * DL);
            int ihi = min(DL, mhi - n * DL);
            float* ob = out + (size_t)n * OROW + ooff + (size_t)wb * DL;
            bool full = (ilo == 0) && (ihi == DL);
            for (int p = tid; p < 128 * DL; p += 256) {
                int w_rel = p / DL, i = p - w_rel * DL;
                if (full || (i >= ilo && i < ihi))
                    ob[p] = Cs[(n * DL + i - m0) * LDC + w_rel];
            }
        }
    }
}

extern "C" void kernel_launch(void* const* d_in, const int* in_sizes, int n_in,
                              void* d_out, int out_size) {
    const float* x  = (const float*)d_in[0];
    const float* W0 = (const float*)d_in[1];
    const float* W1 = (const float*)d_in[2];
    const float* W2 = (const float*)d_in[3];
    float* out = (float*)d_out;

    const int N = in_sizes[0] / XROW;   // 100000

    cudaFuncSetAttribute(tp_mma<1>, cudaFuncAttributeMaxDynamicSharedMemorySize, SMEM_BYTES);
    cudaFuncSetAttribute(tp_mma<3>, cudaFuncAttributeMaxDynamicSharedMemorySize, SMEM_BYTES);
    cudaFuncSetAttribute(tp_mma<5>, cudaFuncAttributeMaxDynamicSharedMemorySize, SMEM_BYTES);

    prep_w<<<(3 * KDIM * WOUT + 255) / 256, 256>>>(W0, W1, W2);

    const int M0 = N, M1 = 3 * N, M2 = 5 * N;
    tp_mma<1><<<dim3(2, (M0 + 127) / 128), 256, SMEM_BYTES>>>(x, out, 0,   0,    0, M0);
    tp_mma<3><<<dim3(2, (M1 + 127) / 128), 256, SMEM_BYTES>>>(x, out, 1,  64,  256, M1);
    tp_mma<5><<<dim3(2, (M2 + 127) / 128), 256, SMEM_BYTES>>>(x, out, 2, 256, 1024, M2);
}

// round 6
// speedup vs baseline: 3.2307x; 1.9016x over previous
#include <cuda_runtime.h>
#include <cuda_fp16.h>
#include <cstdint>

// ---------------------------------------------------------------------------
// E3NN lifting TP: per l, C[M,256] = A[M,64] * W_l[64,256], M = N*(2l+1).
// mma.sync m16n8k16 fp16, 2-term split (x = hi+lo fp16, W = fp16, scale
// folded into W). Persistent CTAs, W resident, A reused across both N-halves,
// register prefetch of next tile, SW128-swizzled smem, coalesced epilogue.
// ---------------------------------------------------------------------------

constexpr int XROW = 576;
constexpr int OROW = 2304;

constexpr int WS_OFF = 0;        // fp16 [256 w][64 u], SW128 rows (128B) = 32 KB
constexpr int AH_OFF = 32768;    // fp16 [128 m][64 u] SW128 = 16 KB
constexpr int AL_OFF = 49152;    // 16 KB
constexpr int CS_OFF = 65536;    // f32 [128][68] = 34816 B
constexpr int LDC    = 68;
constexpr int SMEM_TOTAL = 100352;
constexpr int GRID_P = 296;      // 2 CTAs/SM persistent

// Pre-transposed fp16 weights (scale 1/8 folded in): [l][w][u]
__device__ __align__(16) __half g_W[3][256][64];

__global__ void prep_w(const float* __restrict__ W0, const float* __restrict__ W1,
                       const float* __restrict__ W2) {
    int idx = blockIdx.x * blockDim.x + threadIdx.x;
    if (idx >= 3 * 64 * 256) return;
    int l = idx / (64 * 256);
    int r = idx - l * (64 * 256);
    int u = r >> 8, w = r & 255;
    const float* W = (l == 0) ? W0 : (l == 1) ? W1 : W2;
    g_W[l][w][u] = __float2half_rn(W[u * 256 + w] * 0.125f);  // *0.125 exact
}

__device__ __forceinline__ uint32_t smem_u32(const void* p) {
    uint32_t a;
    asm("{ .reg .u64 t; cvta.to.shared.u64 t, %1; cvt.u32.u64 %0, t; }" : "=r"(a) : "l"(p));
    return a;
}
__device__ __forceinline__ void ldsm_x4(uint32_t addr, uint32_t* r) {
    asm volatile("ldmatrix.sync.aligned.m8n8.x4.shared.b16 {%0,%1,%2,%3}, [%4];"
                 : "=r"(r[0]), "=r"(r[1]), "=r"(r[2]), "=r"(r[3]) : "r"(addr));
}
__device__ __forceinline__ void ldsm_x2(uint32_t addr, uint32_t& r0, uint32_t& r1) {
    asm volatile("ldmatrix.sync.aligned.m8n8.x2.shared.b16 {%0,%1}, [%2];"
                 : "=r"(r0), "=r"(r1) : "r"(addr));
}
__device__ __forceinline__ void mma_f16(float* c, const uint32_t* a,
                                        uint32_t b0, uint32_t b1) {
    asm volatile("mma.sync.aligned.m16n8k16.row.col.f32.f16.f16.f32 "
                 "{%0,%1,%2,%3}, {%4,%5,%6,%7}, {%8,%9}, {%0,%1,%2,%3};"
                 : "+f"(c[0]), "+f"(c[1]), "+f"(c[2]), "+f"(c[3])
                 : "r"(a[0]), "r"(a[1]), "r"(a[2]), "r"(a[3]), "r"(b0), "r"(b1));
}

template <int DL>
__global__ __launch_bounds__(256, 2)
void tp2(const float* __restrict__ x, float* __restrict__ out,
         int lsel, int xoff, int ooff, int Mtot, int ntiles) {
    extern __shared__ char smem[];
    float* Cs = (float*)(smem + CS_OFF);
    const int tid = threadIdx.x, lane = tid & 31, wid = tid >> 5;
    const int wm = wid & 3, wn = wid >> 2;     // warp grid 4(M) x 2(N)

    // ---- stage full W (256 rows, both halves) into SW128 smem, once ----
    {
        const uint4* src = (const uint4*)&g_W[lsel][0][0];   // 2048 x 16B
        #pragma unroll 2
        for (int t = tid; t < 2048; t += 256) {
            int w = t >> 3;
            uint32_t c = (uint32_t)(t & 7) * 16;
            *(uint4*)(smem + WS_OFF + w * 128 + (c ^ ((w & 7) << 4))) = src[t];
        }
    }

    // staging map: u pair = (tid&31)*2, rows smr + it*8
    const int su = (tid & 31) * 2;
    const int smr = tid >> 5;

    // epilogue constants (DL>1)
    int ep_wr[2], ep_ii[2];
    ep_wr[0] = tid / DL;          ep_ii[0] = tid - ep_wr[0] * DL;
    ep_wr[1] = (tid + 256) / DL;  ep_ii[1] = (tid + 256) - ep_wr[1] * DL;

    // ldmatrix lane addressing (SW128: xor mask depends only on row&7)
    const uint32_t sb = smem_u32(smem);
    const int rA = wm * 32 + (lane & 15);
    const uint32_t aBaseH = sb + AH_OFF + rA * 128;
    const uint32_t aBaseL = sb + AL_OFF + rA * 128;
    const uint32_t aXor = (uint32_t)(rA & 7) << 4;
    const uint32_t aCol = (uint32_t)(lane >> 4) * 16;          // + kk*32
    const int rB = wn * 64 + (lane & 7);                       // + half*128 + nn*8
    const uint32_t bXor = (uint32_t)(rB & 7) << 4;
    const uint32_t bCol = (uint32_t)((lane >> 3) & 1) * 16;    // + kk*32

    // ---- prefetch first tile into registers ----
    float2 pf[16];
    {
        const int m0 = blockIdx.x * 128;
        #pragma unroll
        for (int it = 0; it < 16; ++it) {
            int m = m0 + smr + it * 8;
            float v0 = 0.f, v1 = 0.f;
            if (m < Mtot) {
                int n = m / DL, i = m - n * DL;
                const float* p = x + (size_t)n * XROW + xoff + i;
                v0 = p[su * DL];
                v1 = p[(su + 1) * DL];
            }
            pf[it] = make_float2(v0, v1);
        }
    }
    __syncthreads();   // W staged

    for (int mt = blockIdx.x; mt < ntiles; mt += GRID_P) {
        const int m0 = mt * 128;
        const int mhi = min(m0 + 128, Mtot);

        // ---- convert prefetched x -> fp16 hi/lo smem (SW128) ----
        #pragma unroll
        for (int it = 0; it < 16; ++it) {
            int mr = smr + it * 8;
            float v0 = pf[it].x, v1 = pf[it].y;
            __half h0 = __float2half_rn(v0), h1 = __float2half_rn(v1);
            __half l0 = __float2half_rn(v0 - __half2float(h0));
            __half l1 = __float2half_rn(v1 - __half2float(h1));
            uint32_t hp = ((uint32_t)__half_as_ushort(h1) << 16) | __half_as_ushort(h0);
            uint32_t lp = ((uint32_t)__half_as_ushort(l1) << 16) | __half_as_ushort(l0);
            uint32_t off = mr * 128 + (((uint32_t)su * 2) ^ ((mr & 7) << 4));
            *(uint32_t*)(smem + AH_OFF + off) = hp;
            *(uint32_t*)(smem + AL_OFF + off) = lp;
        }
        __syncthreads();

        // ---- prefetch NEXT tile (overlaps MMA + epilogue below) ----
        {
            const int mt2 = mt + GRID_P;
            const int m02 = mt2 * 128;
            const bool vtile = mt2 < ntiles;
            #pragma unroll
            for (int it = 0; it < 16; ++it) {
                int m = m02 + smr + it * 8;
                float v0 = 0.f, v1 = 0.f;
                if (vtile && m < Mtot) {
                    int n = m / DL, i = m - n * DL;
                    const float* p = x + (size_t)n * XROW + xoff + i;
                    v0 = p[su * DL];
                    v1 = p[(su + 1) * DL];
                }
                pf[it] = make_float2(v0, v1);
            }
        }

        // ---- two N-halves, reusing staged A ----
        #pragma unroll 1
        for (int half = 0; half < 2; ++half) {
            float acc[2][8][4];
            #pragma unroll
            for (int mm = 0; mm < 2; ++mm)
                #pragma unroll
                for (int nn = 0; nn < 8; ++nn)
                    #pragma unroll
                    for (int q = 0; q < 4; ++q) acc[mm][nn][q] = 0.f;

            const uint32_t bBase = sb + WS_OFF + (uint32_t)(half * 128 + rB) * 128;

            #pragma unroll
            for (int kk = 0; kk < 4; ++kk) {
                uint32_t ah[2][4], al[2][4];
                const uint32_t ac = (aCol + kk * 32) ^ aXor;
                ldsm_x4(aBaseH + ac,        ah[0]);
                ldsm_x4(aBaseH + 2048 + ac, ah[1]);
                ldsm_x4(aBaseL + ac,        al[0]);
                ldsm_x4(aBaseL + 2048 + ac, al[1]);
                const uint32_t bc = (bCol + kk * 32) ^ bXor;
                #pragma unroll
                for (int nn = 0; nn < 8; ++nn) {
                    uint32_t b0, b1;
                    ldsm_x2(bBase + nn * 1024 + bc, b0, b1);
                    mma_f16(acc[0][nn], ah[0], b0, b1);
                    mma_f16(acc[0][nn], al[0], b0, b1);
                    mma_f16(acc[1][nn], ah[1], b0, b1);
                    mma_f16(acc[1][nn], al[1], b0, b1);
                }
            }

            // ---- epilogue: 2 chunks of 64 cols via Cs, coalesced stores ----
            #pragma unroll 1
            for (int c = 0; c < 2; ++c) {
                if (wn == c) {
                    #pragma unroll
                    for (int mm = 0; mm < 2; ++mm)
                        #pragma unroll
                        for (int nn = 0; nn < 8; ++nn) {
                            int row = wm * 32 + mm * 16 + (lane >> 2);
                            int col = nn * 8 + (lane & 3) * 2;
                            *(float2*)&Cs[row * LDC + col] =
                                make_float2(acc[mm][nn][0], acc[mm][nn][1]);
                            *(float2*)&Cs[(row + 8) * LDC + col] =
                                make_float2(acc[mm][nn][2], acc[mm][nn][3]);
                        }
                }
                __syncthreads();
                const int wgbase = half * 128 + c * 64;   // global w base
                if (DL == 1) {
                    #pragma unroll
                    for (int t8 = 0; t8 < 8; ++t8) {
                        int t = tid + t8 * 256;           // 2048 float4
                        int row = t >> 4, c4 = (t & 15) * 4;
                        int m = m0 + row;
                        if (m < Mtot) {
                            float4 v = *(float4*)&Cs[row * LDC + c4];
                            *(float4*)&out[(size_t)m * OROW + ooff + wgbase + c4] = v;
                        }
                    }
                } else {
                    const int nfirst = m0 / DL;
                    const int nlast = (mhi - 1) / DL;
                    const int rmax = mhi - m0;
                    for (int n = nfirst; n <= nlast; ++n) {
                        float* ob = out + (size_t)n * OROW + ooff + (size_t)wgbase * DL;
                        #pragma unroll
                        for (int j = 0; j < (64 * DL + 255) / 256; ++j) {
                            int p = tid + j * 256;
                            int row = n * DL + ep_ii[j] - m0;
                            if (p < 64 * DL && row >= 0 && row < rmax)
                                ob[p] = Cs[row * LDC + ep_wr[j]];
                        }
                    }
                }
                __syncthreads();
            }
        }
    }
}

extern "C" void kernel_launch(void* const* d_in, const int* in_sizes, int n_in,
                              void* d_out, int out_size) {
    const float* x  = (const float*)d_in[0];
    const float* W0 = (const float*)d_in[1];
    const float* W1 = (const float*)d_in[2];
    const float* W2 = (const float*)d_in[3];
    float* out = (float*)d_out;

    const int N = in_sizes[0] / XROW;   // 100000

    cudaFuncSetAttribute(tp2<1>, cudaFuncAttributeMaxDynamicSharedMemorySize, SMEM_TOTAL);
    cudaFuncSetAttribute(tp2<3>, cudaFuncAttributeMaxDynamicSharedMemorySize, SMEM_TOTAL);
    cudaFuncSetAttribute(tp2<5>, cudaFuncAttributeMaxDynamicSharedMemorySize, SMEM_TOTAL);

    prep_w<<<(3 * 64 * 256 + 255) / 256, 256>>>(W0, W1, W2);

    const int M0 = N, M1 = 3 * N, M2 = 5 * N;
    const int T0 = (M0 + 127) / 128;   // 782
    const int T1 = (M1 + 127) / 128;   // 2344
    const int T2 = (M2 + 127) / 128;   // 3907

    tp2<1><<<GRID_P, 256, SMEM_TOTAL>>>(x, out, 0,   0,    0, M0, T0);
    tp2<3><<<GRID_P, 256, SMEM_TOTAL>>>(x, out, 1,  64,  256, M1, T1);
    tp2<5><<<GRID_P, 256, SMEM_TOTAL>>>(x, out, 2, 256, 1024, M2, T2);
}

// round 9
// speedup vs baseline: 3.4041x; 1.0537x over previous
#include <cuda_runtime.h>
#include <cuda_fp16.h>
#include <cstdint>

// ---------------------------------------------------------------------------
// E3NN lifting TP: per l, C[M,256] = A[M,64] * W_l[64,256], M = N*(2l+1).
// mma.sync m16n8k16 fp16, single-term (x fp16, W fp16 w/ 1/8 folded).
// Error budget: W-rounding + x-rounding each ~2.1e-4 L2 -> ~2.9e-4 total.
// Persistent CTAs, W resident, A staged once/tile reused by both N-halves,
// register prefetch of next tile, SW128 smem, full-width swizzled Cs epilogue.
// ---------------------------------------------------------------------------

constexpr int XROW = 576;
constexpr int OROW = 2304;

constexpr int WS_OFF = 0;        // fp16 [256 w][64 u] SW128 rows = 32 KB
constexpr int AH_OFF = 32768;    // fp16 [128 m][64 u] SW128 = 16 KB
constexpr int CS_OFF = 49152;    // f32 [128][128] XOR-swizzled = 64 KB
constexpr int SMEM_TOTAL = 114688;   // 112 KB -> 2 CTAs/SM
constexpr int GRID_P = 296;

// Pre-transposed fp16 weights (scale 1/8 folded in): [l][w][u]
__device__ __align__(16) __half g_W[3][256][64];

__global__ void prep_w(const float* __restrict__ W0, const float* __restrict__ W1,
                       const float* __restrict__ W2) {
    int idx = blockIdx.x * blockDim.x + threadIdx.x;
    if (idx >= 3 * 64 * 256) return;
    int l = idx / (64 * 256);
    int r = idx - l * (64 * 256);
    int u = r >> 8, w = r & 255;
    const float* W = (l == 0) ? W0 : (l == 1) ? W1 : W2;
    g_W[l][w][u] = __float2half_rn(W[u * 256 + w] * 0.125f);
}

__device__ __forceinline__ uint32_t smem_u32(const void* p) {
    uint32_t a;
    asm("{ .reg .u64 t; cvta.to.shared.u64 t, %1; cvt.u32.u64 %0, t; }" : "=r"(a) : "l"(p));
    return a;
}
__device__ __forceinline__ void ldsm_x4(uint32_t addr, uint32_t* r) {
    asm volatile("ldmatrix.sync.aligned.m8n8.x4.shared.b16 {%0,%1,%2,%3}, [%4];"
                 : "=r"(r[0]), "=r"(r[1]), "=r"(r[2]), "=r"(r[3]) : "r"(addr));
}
__device__ __forceinline__ void ldsm_x2(uint32_t addr, uint32_t& r0, uint32_t& r1) {
    asm volatile("ldmatrix.sync.aligned.m8n8.x2.shared.b16 {%0,%1}, [%2];"
                 : "=r"(r0), "=r"(r1) : "r"(addr));
}
__device__ __forceinline__ void mma_f16(float* c, const uint32_t* a,
                                        uint32_t b0, uint32_t b1) {
    asm volatile("mma.sync.aligned.m16n8k16.row.col.f32.f16.f16.f32 "
                 "{%0,%1,%2,%3}, {%4,%5,%6,%7}, {%8,%9}, {%0,%1,%2,%3};"
                 : "+f"(c[0]), "+f"(c[1]), "+f"(c[2]), "+f"(c[3])
                 : "r"(a[0]), "r"(a[1]), "r"(a[2]), "r"(a[3]), "r"(b0), "r"(b1));
}

template <int DL>
__global__ __launch_bounds__(256, 2)
void tp3(const float* __restrict__ x, float* __restrict__ out,
         int lsel, int xoff, int ooff, int Mtot, int ntiles) {
    extern __shared__ char smem[];
    float* Cs = (float*)(smem + CS_OFF);
    const int tid = threadIdx.x, lane = tid & 31, wid = tid >> 5;
    const int wm = wid & 3, wn = wid >> 2;     // warp grid 4(M) x 2(N)

    // ---- stage full W into SW128 smem, once per persistent CTA ----
    {
        const uint4* src = (const uint4*)&g_W[lsel][0][0];   // 2048 x 16B
        #pragma unroll 2
        for (int t = tid; t < 2048; t += 256) {
            int w = t >> 3;
            uint32_t c = (uint32_t)(t & 7) * 16;
            *(uint4*)(smem + WS_OFF + w * 128 + (c ^ ((w & 7) << 4))) = src[t];
        }
    }

    // staging map: u pair = (tid&31)*2, rows smr + it*8
    const int su = (tid & 31) * 2;
    const int smr = tid >> 5;

    // epilogue constants (DL>1): NJ = ceil(128*DL/256)
    constexpr int NJ = (128 * DL + 255) / 256;
    int ep_wr[NJ], ep_ii[NJ];
    #pragma unroll
    for (int j = 0; j < NJ; ++j) {
        int p = tid + j * 256;
        ep_wr[j] = p / DL;
        ep_ii[j] = p - ep_wr[j] * DL;
    }

    // ldmatrix lane addressing (SW128: xor depends only on row&7)
    const uint32_t sb = smem_u32(smem);
    const int rA = wm * 32 + (lane & 15);
    const uint32_t aBaseH = sb + AH_OFF + rA * 128;
    const uint32_t aXor = (uint32_t)(rA & 7) << 4;
    const uint32_t aCol = (uint32_t)(lane >> 4) * 16;          // + kk*32
    const int rB = wn * 64 + (lane & 7);                       // + half*128 + nn*8
    const uint32_t bXor = (uint32_t)(rB & 7) << 4;
    const uint32_t bCol = (uint32_t)((lane >> 3) & 1) * 16;    // + kk*32

    // ---- prefetch first tile into registers ----
    float2 pf[16];
    {
        const int m0 = blockIdx.x * 128;
        #pragma unroll
        for (int it = 0; it < 16; ++it) {
            int m = m0 + smr + it * 8;
            float v0 = 0.f, v1 = 0.f;
            if (m < Mtot) {
                int n = m / DL, i = m - n * DL;
                const float* p = x + (size_t)n * XROW + xoff + i;
                v0 = p[su * DL];
                v1 = p[(su + 1) * DL];
            }
            pf[it] = make_float2(v0, v1);
        }
    }
    __syncthreads();   // W staged

    for (int mt = blockIdx.x; mt < ntiles; mt += GRID_P) {
        const int m0 = mt * 128;
        const int mhi = min(m0 + 128, Mtot);
        const int rmax = mhi - m0;

        // ---- convert prefetched x -> fp16 smem (SW128) ----
        #pragma unroll
        for (int it = 0; it < 16; ++it) {
            int mr = smr + it * 8;
            uint32_t hp;
            asm("cvt.rn.f16x2.f32 %0, %1, %2;"
                : "=r"(hp) : "f"(pf[it].y), "f"(pf[it].x));   // lo=v0, hi=v1
            uint32_t off = mr * 128 + (((uint32_t)su * 2) ^ ((mr & 7) << 4));
            *(uint32_t*)(smem + AH_OFF + off) = hp;
        }
        __syncthreads();

        // ---- prefetch NEXT tile (overlaps MMA + epilogue) ----
        {
            const int mt2 = mt + GRID_P;
            const int m02 = mt2 * 128;
            const bool vtile = mt2 < ntiles;
            #pragma unroll
            for (int it = 0; it < 16; ++it) {
                int m = m02 + smr + it * 8;
                float v0 = 0.f, v1 = 0.f;
                if (vtile && m < Mtot) {
                    int n = m / DL, i = m - n * DL;
                    const float* p = x + (size_t)n * XROW + xoff + i;
                    v0 = p[su * DL];
                    v1 = p[(su + 1) * DL];
                }
                pf[it] = make_float2(v0, v1);
            }
        }

        // ---- two N-halves, reusing staged A ----
        #pragma unroll 1
        for (int half = 0; half < 2; ++half) {
            float acc[2][8][4];
            #pragma unroll
            for (int mm = 0; mm < 2; ++mm)
                #pragma unroll
                for (int nn = 0; nn < 8; ++nn)
                    #pragma unroll
                    for (int q = 0; q < 4; ++q) acc[mm][nn][q] = 0.f;

            const uint32_t bBase = sb + WS_OFF + (uint32_t)(half * 128 + rB) * 128;

            #pragma unroll
            for (int kk = 0; kk < 4; ++kk) {
                uint32_t ah[2][4];
                const uint32_t ac = (aCol + kk * 32) ^ aXor;
                ldsm_x4(aBaseH + ac,        ah[0]);
                ldsm_x4(aBaseH + 2048 + ac, ah[1]);
                const uint32_t bc = (bCol + kk * 32) ^ bXor;
                #pragma unroll
                for (int nn = 0; nn < 8; ++nn) {
                    uint32_t b0, b1;
                    ldsm_x2(bBase + nn * 1024 + bc, b0, b1);
                    mma_f16(acc[0][nn], ah[0], b0, b1);
                    mma_f16(acc[1][nn], ah[1], b0, b1);
                }
            }

            // ---- epilogue: all warps -> full-width swizzled Cs -> STG ----
            #pragma unroll
            for (int mm = 0; mm < 2; ++mm)
                #pragma unroll
                for (int nn = 0; nn < 8; ++nn) {
                    int row = wm * 32 + mm * 16 + (lane >> 2);
                    int col = wn * 64 + nn * 8 + (lane & 3) * 2;
                    uint32_t cx = (uint32_t)col ^ ((uint32_t)(row & 7) << 2);
                    *(float2*)&Cs[row * 128 + cx] =
                        make_float2(acc[mm][nn][0], acc[mm][nn][1]);
                    *(float2*)&Cs[(row + 8) * 128 + cx] =
                        make_float2(acc[mm][nn][2], acc[mm][nn][3]);
                }
            __syncthreads();

            if (DL == 1) {
                #pragma unroll
                for (int t8 = 0; t8 < 16; ++t8) {
                    int t = tid + t8 * 256;            // 4096 float4
                    int row = t >> 5, c4 = (t & 31) * 4;
                    int m = m0 + row;
                    if (m < Mtot) {
                        uint32_t cx = (uint32_t)c4 ^ ((uint32_t)(row & 7) << 2);
                        float4 v = *(float4*)&Cs[row * 128 + cx];
                        *(float4*)&out[(size_t)m * OROW + ooff + half * 128 + c4] = v;
                    }
                }
            } else {
                const int nfirst = m0 / DL;
                const int nlast = (mhi - 1) / DL;
                for (int n = nfirst; n <= nlast; ++n) {
                    float* ob = out + (size_t)n * OROW + ooff + (size_t)(half * 128) * DL;
                    const int rbase = n * DL - m0;
                    #pragma unroll
                    for (int j = 0; j < NJ; ++j) {
                        int p = tid + j * 256;
                        int row = rbase + ep_ii[j];
                        if (p < 128 * DL && row >= 0 && row < rmax) {
                            uint32_t cx = (uint32_t)ep_wr[j] ^ ((uint32_t)(row & 7) << 2);
                            ob[p] = Cs[row * 128 + cx];
                        }
                    }
                }
            }
            __syncthreads();
        }
    }
}

extern "C" void kernel_launch(void* const* d_in, const int* in_sizes, int n_in,
                              void* d_out, int out_size) {
    const float* x  = (const float*)d_in[0];
    const float* W0 = (const float*)d_in[1];
    const float* W1 = (const float*)d_in[2];
    const float* W2 = (const float*)d_in[3];
    float* out = (float*)d_out;

    const int N = in_sizes[0] / XROW;   // 100000

    cudaFuncSetAttribute(tp3<1>, cudaFuncAttributeMaxDynamicSharedMemorySize, SMEM_TOTAL);
    cudaFuncSetAttribute(tp3<3>, cudaFuncAttributeMaxDynamicSharedMemorySize, SMEM_TOTAL);
    cudaFuncSetAttribute(tp3<5>, cudaFuncAttributeMaxDynamicSharedMemorySize, SMEM_TOTAL);

    prep_w<<<(3 * 64 * 256 + 255) / 256, 256>>>(W0, W1, W2);

    const int M0 = N, M1 = 3 * N, M2 = 5 * N;
    const int T0 = (M0 + 127) / 128;   // 782
    const int T1 = (M1 + 127) / 128;   // 2344
    const int T2 = (M2 + 127) / 128;   // 3907

    tp3<1><<<GRID_P, 256, SMEM_TOTAL>>>(x, out, 0,   0,    0, M0, T0);
    tp3<3><<<GRID_P, 256, SMEM_TOTAL>>>(x, out, 1,  64,  256, M1, T1);
    tp3<5><<<GRID_P, 256, SMEM_TOTAL>>>(x, out, 2, 256, 1024, M2, T2);
}

// round 10
// speedup vs baseline: 4.1508x; 1.2194x over previous
#include <cuda_runtime.h>
#include <cuda_fp16.h>
#include <cstdint>

// ---------------------------------------------------------------------------
// E3NN lifting TP: per l, C[M,256] = A[M,64] * W_l[64,256], M = N*(2l+1).
// mma.sync m16n8k16 fp16 (x fp16, W fp16 w/ 1/8 folded), rel_err ~2.9e-4.
// Tiles DL-aligned (M_TILE in {128,96,80}) so every div/mod is a per-thread
// constant; epilogue stages C in OUTPUT-LINEAR flat order -> reader is just
// LDS.128 + STG.128 per 16B. Persistent CTAs, W resident, reg prefetch.
// ---------------------------------------------------------------------------

constexpr int XROW = 576;
constexpr int OROW = 2304;
constexpr int GRID_P = 296;

// Pre-transposed fp16 weights (scale 1/8 folded in): [l][w][u]
__device__ __align__(16) __half g_W[3][256][64];

__global__ void prep_w(const float* __restrict__ W0, const float* __restrict__ W1,
                       const float* __restrict__ W2) {
    int idx = blockIdx.x * blockDim.x + threadIdx.x;
    if (idx >= 3 * 64 * 256) return;
    int l = idx / (64 * 256);
    int r = idx - l * (64 * 256);
    int u = r >> 8, w = r & 255;
    const float* W = (l == 0) ? W0 : (l == 1) ? W1 : W2;
    g_W[l][w][u] = __float2half_rn(W[u * 256 + w] * 0.125f);
}

__device__ __forceinline__ uint32_t smem_u32(const void* p) {
    uint32_t a;
    asm("{ .reg .u64 t; cvta.to.shared.u64 t, %1; cvt.u32.u64 %0, t; }" : "=r"(a) : "l"(p));
    return a;
}
__device__ __forceinline__ void ldsm_x4(uint32_t addr, uint32_t* r) {
    asm volatile("ldmatrix.sync.aligned.m8n8.x4.shared.b16 {%0,%1,%2,%3}, [%4];"
                 : "=r"(r[0]), "=r"(r[1]), "=r"(r[2]), "=r"(r[3]) : "r"(addr));
}
__device__ __forceinline__ void mma_f16(float* c, const uint32_t* a,
                                        uint32_t b0, uint32_t b1) {
    asm volatile("mma.sync.aligned.m16n8k16.row.col.f32.f16.f16.f32 "
                 "{%0,%1,%2,%3}, {%4,%5,%6,%7}, {%8,%9}, {%0,%1,%2,%3};"
                 : "+f"(c[0]), "+f"(c[1]), "+f"(c[2]), "+f"(c[3])
                 : "r"(a[0]), "r"(a[1]), "r"(a[2]), "r"(a[3]), "r"(b0), "r"(b1));
}

// MTILE multiple of DL and 16; THREADS = 4*MTILE; warps = MTILE/8,
// each warp owns one m16 band: wm = wid>>1 (M), wn = wid&1 (N-half of half).
template <int DL, int MTILE, int THREADS>
__global__ __launch_bounds__(THREADS, 2)
void tp4(const float* __restrict__ x, float* __restrict__ out,
         int lsel, int xoff, int ooff, int Ncap, int ntiles) {
    constexpr int AH_OFF = 32768;                 // after 32KB W
    constexpr int CS_OFF = AH_OFF + MTILE * 128;  // A = MTILE*128B
    constexpr int SPAN = 128 * DL;                // out floats per n per half
    constexpr int ST = THREADS / 32;              // #warps = MTILE/8
    constexpr int NPT = MTILE / DL;               // n rows per tile

    extern __shared__ char smem[];
    const uint32_t sb = smem_u32(smem);
    const int tid = threadIdx.x, lane = tid & 31, wid = tid >> 5;
    const int wm = wid >> 1, wn = wid & 1;

    // ---- stage W into SW128 smem, once ----
    {
        const uint4* src = (const uint4*)&g_W[lsel][0][0];   // 2048 x 16B
        for (int t = tid; t < 2048; t += THREADS) {
            int w = t >> 3;
            uint32_t c = (uint32_t)(t & 7) * 16;
            *(uint4*)(smem + w * 128 + (c ^ ((w & 7) << 4))) = src[t];
        }
    }

    // staging constants (all per-thread invariants)
    const int su = lane * 2;                      // u pair base
    const int mr0 = wid;                          // base row (0..ST-1)
    const int mr0d = mr0 / DL, mr0m = mr0 % DL;

    // writer constants: rows r0, r1 fixed per thread
    const int r0 = wm * 16 + (lane >> 2);
    const int r1 = r0 + 8;
    const int w0 = (r0 / DL) * SPAN + (r0 % DL);  // flat base (DL>1 path)
    const int w1 = (r1 / DL) * SPAN + (r1 % DL);

    // ldmatrix addressing (SW128 xor depends only on row&7)
    const int rA = wm * 16 + (lane & 15);
    const uint32_t aBase = sb + AH_OFF + rA * 128;
    const uint32_t aXor = (uint32_t)(rA & 7) << 4;
    const uint32_t aCol = (uint32_t)(lane >> 4) * 16;
    const int bRow = (lane & 7) + ((lane >> 4) << 3);    // pair-of-n8 x4 layout
    const uint32_t bXor = (uint32_t)(bRow & 7) << 4;
    const uint32_t bCol = (uint32_t)((lane >> 3) & 1) * 16;
    const uint32_t bBase0 = sb + (uint32_t)(wn * 64 + bRow) * 128;

    // ---- prefetch first tile (converted to f16x2 immediately) ----
    uint32_t pf16[8];
    {
        const int nb = blockIdx.x * NPT;
        #pragma unroll
        for (int it = 0; it < 8; ++it) {
            int n = nb + mr0d + it * (ST / DL);
            float v0 = 0.f, v1 = 0.f;
            if (n < Ncap) {
                const float* p = x + (size_t)n * XROW + xoff + mr0m;
                v0 = p[su * DL];
                v1 = p[su * DL + DL];
            }
            asm("cvt.rn.f16x2.f32 %0, %1, %2;" : "=r"(pf16[it]) : "f"(v1), "f"(v0));
        }
    }
    __syncthreads();   // W staged

    for (int mt = blockIdx.x; mt < ntiles; mt += GRID_P) {
        const int n0 = mt * NPT;

        // ---- stage A (SW128 [m][u], fp16) ----
        #pragma unroll
        for (int it = 0; it < 8; ++it) {
            int mr = mr0 + it * ST;
            uint32_t off = (uint32_t)mr * 128 +
                           (((uint32_t)su * 2) ^ ((uint32_t)(mr & 7) << 4));
            *(uint32_t*)(smem + AH_OFF + off) = pf16[it];
        }
        __syncthreads();

        // ---- prefetch NEXT tile (overlaps MMA + epilogue) ----
        {
            const int mt2 = mt + GRID_P;
            const int nb2 = mt2 * NPT;
            const bool vt = mt2 < ntiles;
            #pragma unroll
            for (int it = 0; it < 8; ++it) {
                int n = nb2 + mr0d + it * (ST / DL);
                float v0 = 0.f, v1 = 0.f;
                if (vt && n < Ncap) {
                    const float* p = x + (size_t)n * XROW + xoff + mr0m;
                    v0 = p[su * DL];
                    v1 = p[su * DL + DL];
                }
                asm("cvt.rn.f16x2.f32 %0, %1, %2;" : "=r"(pf16[it]) : "f"(v1), "f"(v0));
            }
        }

        // ---- two N-halves (A reused) ----
        #pragma unroll 1
        for (int half = 0; half < 2; ++half) {
            float acc[8][4];
            #pragma unroll
            for (int nn = 0; nn < 8; ++nn)
                #pragma unroll
                for (int q = 0; q < 4; ++q) acc[nn][q] = 0.f;

            const uint32_t bBase = bBase0 + (uint32_t)(half * 128) * 128;

            #pragma unroll
            for (int kk = 0; kk < 4; ++kk) {
                uint32_t a[4];
                ldsm_x4(aBase + ((aCol + kk * 32) ^ aXor), a);
                const uint32_t bc = (bCol + kk * 32) ^ bXor;
                #pragma unroll
                for (int np = 0; np < 4; ++np) {
                    uint32_t b[4];
                    ldsm_x4(bBase + np * 2048 + bc, b);
                    mma_f16(acc[2 * np],     a, b[0], b[1]);
                    mma_f16(acc[2 * np + 1], a, b[2], b[3]);
                }
            }

            // ---- writer: fragments -> output-linear flat Cs ----
            float* Cs = (float*)(smem + CS_OFF);
            if (DL == 1) {
                // i==0 layout needs swizzle for bank spread
                #pragma unroll
                for (int nn = 0; nn < 8; ++nn) {
                    int c = wn * 64 + nn * 8 + (lane & 3) * 2;
                    *(float2*)&Cs[r0 * 128 + (c ^ ((r0 & 7) << 2))] =
                        make_float2(acc[nn][0], acc[nn][1]);
                    *(float2*)&Cs[r1 * 128 + (c ^ ((r1 & 7) << 2))] =
                        make_float2(acc[nn][2], acc[nn][3]);
                }
            } else {
                #pragma unroll
                for (int nn = 0; nn < 8; ++nn) {
                    int c = wn * 64 + nn * 8 + (lane & 3) * 2;
                    Cs[w0 + c * DL]       = acc[nn][0];
                    Cs[w0 + c * DL + DL]  = acc[nn][1];
                    Cs[w1 + c * DL]       = acc[nn][2];
                    Cs[w1 + c * DL + DL]  = acc[nn][3];
                }
            }
            __syncthreads();

            // ---- reader: flat LDS.128 -> coalesced STG.128 ----
            {
                const float4* Cs4 = (const float4*)(smem + CS_OFF);
                float* ob = out + (size_t)n0 * OROW + ooff + half * SPAN;
                #pragma unroll
                for (int k = 0; k < 8; ++k) {
                    int q = tid + k * THREADS;
                    int nr = q / (32 * DL);
                    int rm = q - nr * (32 * DL);
                    if (n0 + nr < Ncap) {
                        float4 v;
                        if (DL == 1) {
                            int cx = (rm * 4) ^ ((nr & 7) << 2);
                            v = Cs4[nr * 32 + (cx >> 2)];
                        } else {
                            v = Cs4[q];
                        }
                        *(float4*)(ob + nr * OROW + rm * 4) = v;
                    }
                }
            }
            __syncthreads();
        }
    }
}

extern "C" void kernel_launch(void* const* d_in, const int* in_sizes, int n_in,
                              void* d_out, int out_size) {
    const float* x  = (const float*)d_in[0];
    const float* W0 = (const float*)d_in[1];
    const float* W1 = (const float*)d_in[2];
    const float* W2 = (const float*)d_in[3];
    float* out = (float*)d_out;

    const int N = in_sizes[0] / XROW;   // 100000

    constexpr int S1 = 32768 + 128 * 128 + 128 * 512;   // 114688
    constexpr int S3 = 32768 + 96 * 128 + 96 * 512;     //  94208
    constexpr int S5 = 32768 + 80 * 128 + 80 * 512;     //  83968

    cudaFuncSetAttribute(tp4<1, 128, 512>,
                         cudaFuncAttributeMaxDynamicSharedMemorySize, S1);
    cudaFuncSetAttribute(tp4<3, 96, 384>,
                         cudaFuncAttributeMaxDynamicSharedMemorySize, S3);
    cudaFuncSetAttribute(tp4<5, 80, 320>,
                         cudaFuncAttributeMaxDynamicSharedMemorySize, S5);

    prep_w<<<(3 * 64 * 256 + 255) / 256, 256>>>(W0, W1, W2);

    const int T0 = (N + 127) / 128;           // 782 (last partial, guarded)
    const int T1 = (3 * N + 95) / 96;         // 3125 exact
    const int T2 = (5 * N + 79) / 80;         // 6250 exact

    tp4<1, 128, 512><<<GRID_P, 512, S1>>>(x, out, 0,   0,    0, N, T0);
    tp4<3, 96,  384><<<GRID_P, 384, S3>>>(x, out, 1,  64,  256, N, T1);
    tp4<5, 80,  320><<<GRID_P, 320, S5>>>(x, out, 2, 256, 1024, N, T2);
}